// round 14
// baseline (speedup 1.0000x reference)
#include <cuda_runtime.h>
#include <math.h>

#define BB    256
#define T2V   1026
#define TP1   1025
#define NVOC  35
#define H7    224
#define HN    (BB*1024)
#define EPSV  2.220446049250313e-16f
#define LOG2E 1.4426950408889634f
#define LN2   0.6931471805599453f
#define FULLM 0xffffffffu
#define NT    128

// ---------------- device scratch (small scalars only) ----------------
static __device__ float g_prex[NVOC * H7];
static __device__ float g_intA[BB], g_intB[BB], g_mskA[BB], g_mskB[BB];
static __device__ float g_loglam[BB], g_nev[BB];

// ---------------- fast math ----------------
__device__ __forceinline__ float ex2f(float x){ float r; asm("ex2.approx.f32 %0,%1;":"=f"(r):"f"(x)); return r; }
__device__ __forceinline__ float lg2f(float x){ float r; asm("lg2.approx.f32 %0,%1;":"=f"(r):"f"(x)); return r; }
__device__ __forceinline__ float rcpf(float x){ float r; asm("rcp.approx.f32 %0,%1;":"=f"(r):"f"(x)); return r; }
__device__ __forceinline__ float sig_fast(float x){
    float s = ex2f(-fabsf(x) * LOG2E);
    float r = rcpf(1.0f + s);
    return x >= 0.0f ? r : s * r;
}
__device__ __forceinline__ float tanh_fast(float x){
    float s2 = ex2f(-2.0f * LOG2E * fabsf(x));
    float tv = (1.0f - s2) * rcpf(1.0f + s2);
    return x >= 0.0f ? tv : -tv;
}
__device__ __forceinline__ float softplus_fast(float x){
    return fmaxf(x, 0.0f) + lg2f(1.0f + ex2f(-fabsf(x) * LOG2E)) * LN2;
}
__device__ __forceinline__ float softplus_log2(float x){   // softplus(x)/ln2
    return fmaxf(x, 0.0f) * LOG2E + lg2f(1.0f + ex2f(-fabsf(x) * LOG2E));
}
__device__ __forceinline__ unsigned su32(const void* p){
    unsigned a;
    asm("{ .reg .u64 t; cvta.to.shared.u64 t, %1; cvt.u32.u64 %0, t; }" : "=r"(a) : "l"(p));
    return a;
}

// ---------------- SMEM layout (float offsets; 16B-aligned blocks) ----------
#define OFF_PREX 0        /* 35*224 = 7840 */
#define OFF_RC   7840     /* ring c     64*32 */
#define OFF_RCB  9888     /* ring cbar  64*32 */
#define OFF_RL   11936    /* ring delta 64*32 */
#define OFF_RO   13984    /* ring o     64*32 */
#define OFF_RH   16032    /* ring h     64*32 */
#define OFF_DT   18080    /* dtime row 1026 (+pad) */
#define OFF_EV   19108    /* event row 1026 (int) */
#define OFF_DTS  20136    /* dts row  1025 (+pad) */
#define OFF_MSK  21164    /* mask row 1025 (+pad) */
#define OFF_WLP  22192    /* Wl padded 32*33 */
#define OFF_ACT  23248    /* act 224 */
#define OFF_HD   23472    /* h duplicated 64 (pairs) */
#define OFF_E    23536    /* decay e 32 */
#define OFF_SHCH 23568    /* per-warp ch transpose 4*32 */
#define OFF_RED  23696    /* reduction 8 */
#define SMEM_FLOATS 23712
#define SMEM_BYTES  (SMEM_FLOATS * 4)

// ---------------- kernel A: prex[v][j] = Emb[v]·Wx[:,j] + b[j] -------------
__global__ void k_prex(const float* __restrict__ Emb,
                       const float* __restrict__ W,
                       const float* __restrict__ bias) {
    int v = blockIdx.x;
    int j = threadIdx.x;
    float acc = bias[j];
    #pragma unroll
    for (int k = 0; k < 32; k++)
        acc += Emb[v * 32 + k] * W[k * H7 + j];
    g_prex[v * H7 + j] = acc;
}

// ---------------- kernel B: fused scan, 4-warp gate-paired -----------------
// warp 0: gates (i, ib)   columns lane,      128+lane   (packed f32x2 dot)
// warp 1: gates (f, fb)   columns 32+lane,   160+lane
// warp 2: gates (z, delta) columns 64+lane,  192+lane
// warp 3: gate  o (scalar) column 96+lane  + owns phase 2 (cell update)
__global__ void __launch_bounds__(NT, 2)
k_scan(const int*   __restrict__ event,
       const float* __restrict__ dtime,
       const float* __restrict__ W,
       const float* __restrict__ Wl,
       const float* __restrict__ dts,
       const float* __restrict__ mask,
       float*       __restrict__ lam_out) {
    extern __shared__ float sm[];
    const int b    = blockIdx.x;
    const int j    = threadIdx.x;
    const int w    = j >> 5;
    const int lane = j & 31;

    float* prex  = sm + OFF_PREX;
    float* ringc = sm + OFF_RC;
    float* ringcb= sm + OFF_RCB;
    float* ringL = sm + OFF_RL;
    float* ringo = sm + OFF_RO;
    float* ringh = sm + OFF_RH;
    float* dt_sh = sm + OFF_DT;
    int*   ev_sh = (int*)(sm + OFF_EV);
    float* dts_sh= sm + OFF_DTS;
    float* msk_sh= sm + OFF_MSK;
    float* wlp   = sm + OFF_WLP;
    float* act   = sm + OFF_ACT;
    float* h_dup = sm + OFF_HD;
    float* e_sh  = sm + OFF_E;
    float* shch  = sm + OFF_SHCH;
    float* red   = sm + OFF_RED;

    const int f0      = b * TP1;
    const int validTp = (HN - f0 < TP1) ? (HN - f0) : TP1;

    // -------- init: stage everything into SMEM once --------
    for (int i = j; i < NVOC * H7; i += NT) prex[i] = g_prex[i];
    for (int i = j; i < T2V; i += NT) {
        dt_sh[i] = dtime[b * T2V + i];
        ev_sh[i] = event[b * T2V + i];
    }
    for (int i = j; i < TP1; i += NT) {
        bool ok = (f0 + i) < HN;
        dts_sh[i] = ok ? dts[f0 + i]  : 0.0f;
        msk_sh[i] = ok ? mask[f0 + i] : 0.0f;
    }
    for (int i = j; i < 1024; i += NT)
        wlp[(i >> 5) * 33 + (i & 31)] = Wl[i];

    // column indices
    const int j1 = 32 * w + lane;              // first gate column
    const int j2 = 32 * (w + 4) + lane;        // second gate column (w<3)

    // packed weights (w<3): wp2[k] = (W_h[k][j1], W_h[k][j2]); w3: scalar
    unsigned long long wp2[32];
    float wco[32];
    if (w < 3) {
        #pragma unroll
        for (int k = 0; k < 32; k++) {
            float wa = W[(32 + k) * H7 + j1];
            float wb = W[(32 + k) * H7 + j2];
            asm("mov.b64 %0, {%1,%2};" : "=l"(wp2[k]) : "f"(wa), "f"(wb));
        }
    } else {
        #pragma unroll
        for (int k = 0; k < 32; k++)
            wco[k] = W[(32 + k) * H7 + j1];
    }

    // sampler weights: lane e keeps Wl[e][:]
    float wle[32];
    {
        const float4* wl4 = (const float4*)(Wl + lane * 32);
        #pragma unroll
        for (int p = 0; p < 8; p++) {
            float4 wv = wl4[p];
            wle[4*p+0] = wv.x; wle[4*p+1] = wv.y;
            wle[4*p+2] = wv.z; wle[4*p+3] = wv.w;
        }
    }

    if (j < 64) h_dup[j] = 0.0f;
    float cm = 0.0f, cbm = 0.0f;               // carries (warp 3)
    float acc0 = 0.f, acc1 = 0.f, am0 = 0.f, am1 = 0.f;  // integral groups
    float accL = 0.f, accN = 0.f;              // target loglambda

    const unsigned hb = su32(h_dup);

    __syncthreads();

    float px1 = prex[ev_sh[0] * H7 + j1];
    float px2 = (w < 3) ? prex[ev_sh[0] * H7 + j2] : 0.0f;

    // -------- chunk processor: sampling + target for steps [t0, t0+cnt) ----
    auto chunk = [&](int t0, int cnt) {
        for (int rr = w; rr < cnt; rr += 4) {
            int trow = t0 + rr;
            int base = (trow & 63) * 32 + lane;

            // ---- target log-lambda (all steps) ----
            {
                int tgt = ev_sh[trow + 1];
                bool mm = (tgt < 32);
                int  tt = mm ? tgt : 0;
                float p = ringh[base] * wlp[tt * 33 + lane];
                #pragma unroll
                for (int o = 16; o > 0; o >>= 1) p += __shfl_down_sync(FULLM, p, o);
                if (lane == 0 && mm) {
                    accL += lg2f(softplus_fast(p) + EPSV) * LN2;
                    accN += 1.0f;
                }
            }
            // ---- MC sample row (only valid flat rows) ----
            if (trow < validTp) {
                float c  = ringc [base];
                float cb = ringcb[base];
                float L  = ringL [base];
                float o  = ringo [base];
                float dtv = dts_sh[trow];
                float m   = msk_sh[trow];

                float cd = fmaf(c - cb, ex2f(-L * dtv), cb);
                float ch = o * tanh_fast(cd);
                shch[w * 32 + lane] = ch;
                __syncwarp();

                float d0 = 0.f, d1 = 0.f, d2 = 0.f, d3 = 0.f;
                const float4* c4 = (const float4*)(shch + w * 32);
                #pragma unroll
                for (int p = 0; p < 8; p++) {
                    float4 cv = c4[p];                 // broadcast
                    d0 = fmaf(cv.x, wle[4*p+0], d0);
                    d1 = fmaf(cv.y, wle[4*p+1], d1);
                    d2 = fmaf(cv.z, wle[4*p+2], d2);
                    d3 = fmaf(cv.w, wle[4*p+3], d3);
                }
                float sp = softplus_fast((d0 + d1) + (d2 + d3));
                lam_out[(size_t)(f0 + trow) * 32 + lane] = sp;

                if (b + trow < 1024) { acc0 += sp * m; if (lane == 0) am0 += m; }
                else                 { acc1 += sp * m; if (lane == 0) am1 += m; }
                __syncwarp();
            }
        }
    };

    // -------- one scan step --------
    auto step = [&](int t, bool last) {
        int sl = (t & 63) * 32 + lane;
        if (w < 3) {
            // packed dot: lo accumulates j1's dot, hi j2's
            unsigned long long p0, p1, p2, p3;
            asm("mov.b64 %0, {%1,%2};" : "=l"(p0) : "f"(px1), "f"(px2));
            asm("mov.b64 %0, 0;" : "=l"(p1));
            asm("mov.b64 %0, 0;" : "=l"(p2));
            asm("mov.b64 %0, 0;" : "=l"(p3));
            #pragma unroll
            for (int q = 0; q < 8; q++) {
                unsigned long long hA, hB;      // (h2q,h2q) and (h2q+1,h2q+1)
                asm volatile("ld.shared.v2.b64 {%0,%1},[%2];" : "=l"(hA), "=l"(hB) : "r"(hb + 16 * q));
                unsigned long long hC, hD;
                asm volatile("ld.shared.v2.b64 {%0,%1},[%2];" : "=l"(hC), "=l"(hD) : "r"(hb + 16 * q + 128));
                asm("fma.rn.f32x2 %0,%1,%2,%0;" : "+l"(p0) : "l"(hA), "l"(wp2[2*q+0]));
                asm("fma.rn.f32x2 %0,%1,%2,%0;" : "+l"(p1) : "l"(hB), "l"(wp2[2*q+1]));
                asm("fma.rn.f32x2 %0,%1,%2,%0;" : "+l"(p2) : "l"(hC), "l"(wp2[2*q+16]));
                asm("fma.rn.f32x2 %0,%1,%2,%0;" : "+l"(p3) : "l"(hD), "l"(wp2[2*q+17]));
            }
            asm("add.rn.f32x2 %0,%0,%1;" : "+l"(p0) : "l"(p1));
            asm("add.rn.f32x2 %0,%0,%1;" : "+l"(p2) : "l"(p3));
            asm("add.rn.f32x2 %0,%0,%1;" : "+l"(p0) : "l"(p2));
            float pre1, pre2;
            asm("mov.b64 {%0,%1},%2;" : "=f"(pre1), "=f"(pre2) : "l"(p0));

            if (w == 2) {                       // z, delta
                act[j1] = tanh_fast(pre1);
                float dL = softplus_log2(pre2);
                e_sh[lane] = ex2f(-dL * dt_sh[t + 1]);
                ringL[sl] = dL;
            } else {                            // (i,ib) or (f,fb)
                act[j1] = sig_fast(pre1);
                act[j2] = sig_fast(pre2);
            }
            if (!last) {
                px1 = prex[ev_sh[t + 1] * H7 + j1];
                px2 = prex[ev_sh[t + 1] * H7 + j2];
            }
            __syncthreads();                    // gates ready
            __syncthreads();                    // h ready (phase 2 done)
        } else {
            // warp 3: scalar o-gate dot
            float a0 = px1, a1 = 0.f, a2 = 0.f, a3 = 0.f;
            #pragma unroll
            for (int q = 0; q < 16; q++) {
                float4 hv;                       // (h2q,h2q,h2q+1,h2q+1)
                asm volatile("ld.shared.v4.f32 {%0,%1,%2,%3},[%4];"
                    : "=f"(hv.x), "=f"(hv.y), "=f"(hv.z), "=f"(hv.w) : "r"(hb + 16 * q));
                if (q & 1) { a2 = fmaf(hv.x, wco[2*q], a2); a3 = fmaf(hv.z, wco[2*q+1], a3); }
                else       { a0 = fmaf(hv.x, wco[2*q], a0); a1 = fmaf(hv.z, wco[2*q+1], a1); }
            }
            float ov = sig_fast((a0 + a1) + (a2 + a3));
            ringo[sl] = ov;
            if (!last) px1 = prex[ev_sh[t + 1] * H7 + j1];

            __syncthreads();                    // wait for gate warps

            // phase 2: cell update (o in register)
            float iv  = act[lane];
            float fv  = act[32  + lane];
            float zv  = act[64  + lane];
            float ibv = act[128 + lane];
            float fbv = act[160 + lane];
            float e   = e_sh[lane];

            float c  = fmaf(fv,  cm,  iv  * zv);
            float cb = fmaf(fbv, cbm, ibv * zv);
            float cn = fmaf(c - cb, e, cb);
            float h  = ov * tanh_fast(cn);

            // h duplicated pair store: h_dup[2*lane], h_dup[2*lane+1]
            asm volatile("st.shared.v2.f32 [%0],{%1,%2};" :: "r"(hb + 8 * lane), "f"(h), "f"(h));
            ringc [sl] = c;
            ringcb[sl] = cb;
            ringh [sl] = h;

            cm = cn; cbm = cb;
            __syncthreads();                    // release gate warps
        }
    };

    // ---------------- main loop: 16 blocks of 64 + 1 tail step --------------
    for (int blk = 0; blk < 16; blk++) {
        int t0 = blk * 64;
        #pragma unroll 1
        for (int i = 0; i < 64; i++) step(t0 + i, false);
        chunk(t0, 64);
        __syncthreads();                        // ring drained before overwrite
    }
    step(1024, true);
    chunk(1024, 1);
    __syncthreads();

    // ---------------- epilogue: block reductions (4 warps) -----------------
    auto bred = [&](float v) -> float {
        #pragma unroll
        for (int o = 16; o > 0; o >>= 1) v += __shfl_down_sync(FULLM, v, o);
        if (lane == 0) red[w] = v;
        __syncthreads();
        float r = 0.0f;
        if (j == 0) {
            #pragma unroll
            for (int k = 0; k < 4; k++) r += red[k];
        }
        __syncthreads();
        return r;
    };

    float s;
    s = bred(acc0); if (j == 0) g_intA[b] = s;
    s = bred(acc1); if (j == 0) g_intB[b] = s;
    s = bred(am0);  if (j == 0) g_mskA[b] = s;
    s = bred(am1);  if (j == 0) g_mskB[b] = s;
    s = bred(accL); if (j == 0) g_loglam[b] = s;
    s = bred(accN); if (j == 0) g_nev[b] = s;
}

// ---------------- final: stitch integral groups + reduce scalars ----------
__global__ void __launch_bounds__(256)
k_final(const float* __restrict__ dur, float* __restrict__ out) {
    const int bb = threadIdx.x;     // one thread per group
    __shared__ float red[8];

    float lamsum = g_intA[bb] + (bb > 0 ? g_intB[bb - 1] : 0.0f);
    float msum   = g_mskA[bb] + (bb > 0 ? g_mskB[bb - 1] : 0.0f);
    float integ  = __fdividef(lamsum, msum) * dur[bb];
    float lp = g_loglam[bb] - integ;
    float nv = g_nev[bb];

    int wid = threadIdx.x >> 5, lid = threadIdx.x & 31;
    #pragma unroll
    for (int o = 16; o > 0; o >>= 1) lp += __shfl_down_sync(FULLM, lp, o);
    if (lid == 0) red[wid] = lp;
    __syncthreads();
    if (wid == 0) {
        float v = (lid < 8) ? red[lid] : 0.0f;
        #pragma unroll
        for (int o = 4; o > 0; o >>= 1) v += __shfl_down_sync(FULLM, v, o);
        if (lid == 0) out[0] = -v;
    }
    __syncthreads();
    #pragma unroll
    for (int o = 16; o > 0; o >>= 1) nv += __shfl_down_sync(FULLM, nv, o);
    if (lid == 0) red[wid] = nv;
    __syncthreads();
    if (wid == 0) {
        float v = (lid < 8) ? red[lid] : 0.0f;
        #pragma unroll
        for (int o = 4; o > 0; o >>= 1) v += __shfl_down_sync(FULLM, v, o);
        if (lid == 0) out[1] = v;
    }
}

// ---------------- launch ----------------
extern "C" void kernel_launch(void* const* d_in, const int* in_sizes, int n_in,
                              void* d_out, int out_size) {
    const int*   event = (const int*)  d_in[0];
    const float* dtime = (const float*)d_in[1];
    const float* dur   = (const float*)d_in[2];
    const float* dts   = (const float*)d_in[3];
    // d_in[4] = index_of_hidden_sampling (unused by the reference)
    const float* mask  = (const float*)d_in[5];
    const float* Emb   = (const float*)d_in[6];
    const float* W     = (const float*)d_in[7];
    const float* bias  = (const float*)d_in[8];
    const float* Wl    = (const float*)d_in[9];

    float* out = (float*)d_out;
    long long lam_elems = (long long)HN * 32;
    long long lamoff = (long long)out_size - lam_elems;
    if (lamoff < 0) lamoff = 0;
    float* lam_out = out + lamoff;

    static int attr_set = 0;
    if (!attr_set) {
        cudaFuncSetAttribute(k_scan, cudaFuncAttributeMaxDynamicSharedMemorySize,
                             SMEM_BYTES);
        attr_set = 1;
    }

    k_prex <<<NVOC, H7>>>(Emb, W, bias);
    k_scan <<<BB, NT, SMEM_BYTES>>>(event, dtime, W, Wl, dts, mask, lam_out);
    k_final<<<1, 256>>>(dur, out);
}

// round 15
// speedup vs baseline: 1.0884x; 1.0884x over previous
#include <cuda_runtime.h>
#include <math.h>

#define BB    256
#define T2V   1026
#define TP1   1025
#define NVOC  35
#define H7    224
#define HN    (BB*1024)
#define EPSV  2.220446049250313e-16f
#define LOG2E 1.4426950408889634f
#define LN2   0.6931471805599453f
#define FULLM 0xffffffffu
#define NT    224

// ---------------- device scratch (small scalars only) ----------------
static __device__ float g_prex[NVOC * H7];
static __device__ float g_intA[BB], g_intB[BB], g_mskA[BB], g_mskB[BB];
static __device__ float g_loglam[BB], g_nev[BB];

// ---------------- fast math ----------------
__device__ __forceinline__ float ex2f(float x){ float r; asm("ex2.approx.f32 %0,%1;":"=f"(r):"f"(x)); return r; }
__device__ __forceinline__ float lg2f(float x){ float r; asm("lg2.approx.f32 %0,%1;":"=f"(r):"f"(x)); return r; }
__device__ __forceinline__ float rcpf(float x){ float r; asm("rcp.approx.f32 %0,%1;":"=f"(r):"f"(x)); return r; }
__device__ __forceinline__ float sig_fast(float x){
    float s = ex2f(-fabsf(x) * LOG2E);
    float r = rcpf(1.0f + s);
    return x >= 0.0f ? r : s * r;
}
__device__ __forceinline__ float tanh_fast(float x){
    float s2 = ex2f(-2.0f * LOG2E * fabsf(x));
    float tv = (1.0f - s2) * rcpf(1.0f + s2);
    return x >= 0.0f ? tv : -tv;
}
__device__ __forceinline__ float softplus_fast(float x){
    return fmaxf(x, 0.0f) + lg2f(1.0f + ex2f(-fabsf(x) * LOG2E)) * LN2;
}
__device__ __forceinline__ float softplus_log2(float x){   // softplus(x)/ln2
    return fmaxf(x, 0.0f) * LOG2E + lg2f(1.0f + ex2f(-fabsf(x) * LOG2E));
}
__device__ __forceinline__ unsigned su32(const void* p){
    unsigned a;
    asm("{ .reg .u64 t; cvta.to.shared.u64 t, %1; cvt.u32.u64 %0, t; }" : "=r"(a) : "l"(p));
    return a;
}

// ---------------- SMEM layout (float offsets; 16B-aligned blocks) ----------
#define OFF_PREX 0        /* 35*224 = 7840 */
#define OFF_RC   7840     /* ring c     64*32 */
#define OFF_RCB  9888     /* ring cbar  64*32 */
#define OFF_RL   11936    /* ring delta 64*32 */
#define OFF_RO   13984    /* ring o     64*32 */
#define OFF_RH   16032    /* ring h     64*32 */
#define OFF_DT   18080    /* dtime row 1026 (+pad) */
#define OFF_EV   19108    /* event row 1026 (int) */
#define OFF_DTS  20136    /* dts row  1025 (+pad) */
#define OFF_MSK  21164    /* mask row 1025 (+pad) */
#define OFF_WLP  22192    /* Wl padded 32*33 (1056) */
#define OFF_ACT  23248    /* act double-buffered 2*224 */
#define OFF_HW   23696    /* per-warp private h rows 7*32 */
#define OFF_E    23920    /* decay e double-buffered 2*32 */
#define OFF_SHCH 23984    /* per-warp ch transpose 7*32 */
#define OFF_RED  24208    /* reduction 8 */
#define SMEM_FLOATS 24216
#define SMEM_BYTES  (SMEM_FLOATS * 4)

// ---------------- kernel A: prex[v][j] = Emb[v]·Wx[:,j] + b[j] -------------
__global__ void k_prex(const float* __restrict__ Emb,
                       const float* __restrict__ W,
                       const float* __restrict__ bias) {
    int v = blockIdx.x;
    int j = threadIdx.x;
    float acc = bias[j];
    #pragma unroll
    for (int k = 0; k < 32; k++)
        acc += Emb[v * 32 + k] * W[k * H7 + j];
    g_prex[v * H7 + j] = acc;
}

// ---------------- kernel B: fused scan, ONE barrier/step -------------------
// 7 uniform gate warps (R12 mapping). Phase 2 computed redundantly by every
// warp; h kept in a per-warp private SMEM row -> h dependency is intra-warp.
__global__ void __launch_bounds__(NT, 2)
k_scan(const int*   __restrict__ event,
       const float* __restrict__ dtime,
       const float* __restrict__ W,
       const float* __restrict__ Wl,
       const float* __restrict__ dts,
       const float* __restrict__ mask,
       float*       __restrict__ lam_out) {
    extern __shared__ float sm[];
    const int b    = blockIdx.x;
    const int j    = threadIdx.x;
    const int w    = j >> 5;
    const int lane = j & 31;

    float* prex  = sm + OFF_PREX;
    float* ringc = sm + OFF_RC;
    float* ringcb= sm + OFF_RCB;
    float* ringL = sm + OFF_RL;
    float* ringo = sm + OFF_RO;
    float* ringh = sm + OFF_RH;
    float* dt_sh = sm + OFF_DT;
    int*   ev_sh = (int*)(sm + OFF_EV);
    float* dts_sh= sm + OFF_DTS;
    float* msk_sh= sm + OFF_MSK;
    float* wlp   = sm + OFF_WLP;
    float* act   = sm + OFF_ACT;      // [2][224]
    float* hw    = sm + OFF_HW;       // [7][32] per-warp private h
    float* e_sh  = sm + OFF_E;        // [2][32]
    float* shch  = sm + OFF_SHCH;
    float* red   = sm + OFF_RED;

    const int f0      = b * TP1;
    const int validTp = (HN - f0 < TP1) ? (HN - f0) : TP1;

    // -------- init: stage everything into SMEM once --------
    for (int i = j; i < NVOC * H7; i += NT) prex[i] = g_prex[i];
    for (int i = j; i < T2V; i += NT) {
        dt_sh[i] = dtime[b * T2V + i];
        ev_sh[i] = event[b * T2V + i];
    }
    for (int i = j; i < TP1; i += NT) {
        bool ok = (f0 + i) < HN;
        dts_sh[i] = ok ? dts[f0 + i]  : 0.0f;
        msk_sh[i] = ok ? mask[f0 + i] : 0.0f;
    }
    for (int i = j; i < 1024; i += NT)
        wlp[(i >> 5) * 33 + (i & 31)] = Wl[i];

    // packed recurrent weight column: wp[k] = (W_h[2k][j], W_h[2k+1][j])
    unsigned long long wp[16];
    #pragma unroll
    for (int k = 0; k < 16; k++) {
        float wlo = W[(32 + 2 * k)     * H7 + j];
        float whi = W[(32 + 2 * k + 1) * H7 + j];
        asm("mov.b64 %0, {%1,%2};" : "=l"(wp[k]) : "f"(wlo), "f"(whi));
    }

    // sampler weights: lane e keeps Wl[e][:]
    float wle[32];
    {
        const float4* wl4 = (const float4*)(Wl + lane * 32);
        #pragma unroll
        for (int p = 0; p < 8; p++) {
            float4 wv = wl4[p];
            wle[4*p+0] = wv.x; wle[4*p+1] = wv.y;
            wle[4*p+2] = wv.z; wle[4*p+3] = wv.w;
        }
    }

    if (j < 7 * 32) hw[j] = 0.0f;
    float cm = 0.0f, cbm = 0.0f;               // carries (replicated per warp)
    float acc0 = 0.f, acc1 = 0.f, am0 = 0.f, am1 = 0.f;  // integral groups
    float accL = 0.f, accN = 0.f;              // target loglambda

    const unsigned hb = su32(hw) + w * 128;    // this warp's private h row

    __syncthreads();

    float px = prex[ev_sh[0] * H7 + j];

    // -------- chunk processor: sampling + target for steps [t0, t0+cnt) ----
    auto chunk = [&](int t0, int cnt) {
        for (int rr = w; rr < cnt; rr += 7) {
            int trow = t0 + rr;
            int base = (trow & 63) * 32 + lane;

            // ---- target log-lambda (all steps) ----
            {
                int tgt = ev_sh[trow + 1];
                bool mm = (tgt < 32);
                int  tt = mm ? tgt : 0;
                float p = ringh[base] * wlp[tt * 33 + lane];
                #pragma unroll
                for (int o = 16; o > 0; o >>= 1) p += __shfl_down_sync(FULLM, p, o);
                if (lane == 0 && mm) {
                    accL += lg2f(softplus_fast(p) + EPSV) * LN2;
                    accN += 1.0f;
                }
            }
            // ---- MC sample row (only valid flat rows) ----
            if (trow < validTp) {
                float c  = ringc [base];
                float cb = ringcb[base];
                float L  = ringL [base];
                float o  = ringo [base];
                float dtv = dts_sh[trow];
                float m   = msk_sh[trow];

                float cd = fmaf(c - cb, ex2f(-L * dtv), cb);
                float ch = o * tanh_fast(cd);
                shch[w * 32 + lane] = ch;
                __syncwarp();

                float d0 = 0.f, d1 = 0.f, d2 = 0.f, d3 = 0.f;
                const float4* c4 = (const float4*)(shch + w * 32);
                #pragma unroll
                for (int p = 0; p < 8; p++) {
                    float4 cv = c4[p];                 // broadcast
                    d0 = fmaf(cv.x, wle[4*p+0], d0);
                    d1 = fmaf(cv.y, wle[4*p+1], d1);
                    d2 = fmaf(cv.z, wle[4*p+2], d2);
                    d3 = fmaf(cv.w, wle[4*p+3], d3);
                }
                float sp = softplus_fast((d0 + d1) + (d2 + d3));
                lam_out[(size_t)(f0 + trow) * 32 + lane] = sp;

                if (b + trow < 1024) { acc0 += sp * m; if (lane == 0) am0 += m; }
                else                 { acc1 += sp * m; if (lane == 0) am1 += m; }
                __syncwarp();
            }
        }
    };

    // -------- one scan step: ONE barrier ----------------------------------
    auto step = [&](int t, bool last) {
        int buf = (t & 1);
        int sl  = (t & 63) * 32 + lane;

        // phase 1: packed-f32x2 dot on own private h row
        unsigned long long pacc0, pacc1, pacc2, pacc3;
        asm("mov.b64 %0, {%1,%2};" : "=l"(pacc0) : "f"(px), "f"(0.0f));
        asm("mov.b64 %0, 0;" : "=l"(pacc1));
        asm("mov.b64 %0, 0;" : "=l"(pacc2));
        asm("mov.b64 %0, 0;" : "=l"(pacc3));
        #pragma unroll
        for (int q = 0; q < 4; q++) {
            unsigned long long hA, hB, hC, hD;
            asm volatile("ld.shared.v2.b64 {%0,%1},[%2];" : "=l"(hA), "=l"(hB) : "r"(hb + 32 * q));
            asm volatile("ld.shared.v2.b64 {%0,%1},[%2];" : "=l"(hC), "=l"(hD) : "r"(hb + 32 * q + 16));
            asm("fma.rn.f32x2 %0,%1,%2,%0;" : "+l"(pacc0) : "l"(hA), "l"(wp[4*q+0]));
            asm("fma.rn.f32x2 %0,%1,%2,%0;" : "+l"(pacc1) : "l"(hB), "l"(wp[4*q+1]));
            asm("fma.rn.f32x2 %0,%1,%2,%0;" : "+l"(pacc2) : "l"(hC), "l"(wp[4*q+2]));
            asm("fma.rn.f32x2 %0,%1,%2,%0;" : "+l"(pacc3) : "l"(hD), "l"(wp[4*q+3]));
        }
        asm("add.rn.f32x2 %0,%0,%1;" : "+l"(pacc0) : "l"(pacc1));
        asm("add.rn.f32x2 %0,%0,%1;" : "+l"(pacc2) : "l"(pacc3));
        asm("add.rn.f32x2 %0,%0,%1;" : "+l"(pacc0) : "l"(pacc2));
        float plo, phi;
        asm("mov.b64 {%0,%1},%2;" : "=f"(plo), "=f"(phi) : "l"(pacc0));
        float pre = plo + phi;

        float a;
        if (w == 2) {                          // z: tanh
            a = tanh_fast(pre);
            act[buf * 224 + j] = a;
        } else if (w == 6) {                   // delta: softplus (log2 domain)
            a = softplus_log2(pre);
            e_sh[buf * 32 + lane] = ex2f(-a * dt_sh[t + 1]);
            ringL[sl] = a;                     // act slot unused for delta
        } else {                               // i,f,o,ib,fb: sigmoid
            a = sig_fast(pre);
            act[buf * 224 + j] = a;
            if (w == 3) ringo[sl] = a;
        }

        // prefetch next step's pre-x term
        if (!last) px = prex[ev_sh[t + 1] * H7 + j];

        __syncthreads();                       // the ONLY per-step barrier

        // phase 2: redundant cell update in EVERY warp (private h row)
        {
            const float* A = act + buf * 224;
            float iv  = A[lane];
            float fv  = A[32  + lane];
            float zv  = A[64  + lane];
            float ov  = A[96  + lane];
            float ibv = A[128 + lane];
            float fbv = A[160 + lane];
            float e   = e_sh[buf * 32 + lane];

            float c  = fmaf(fv,  cm,  iv  * zv);
            float cb = fmaf(fbv, cbm, ibv * zv);
            float cn = fmaf(c - cb, e, cb);
            float h  = ov * tanh_fast(cn);

            hw[w * 32 + lane] = h;             // own row: no barrier needed
            if (w == 0) {
                ringc [sl] = c;
                ringcb[sl] = cb;
                ringh [sl] = h;
            }
            cm = cn; cbm = cb;
        }
    };

    // ---------------- main loop: 16 blocks of 64 + 1 tail step --------------
    for (int blk = 0; blk < 16; blk++) {
        int t0 = blk * 64;
        #pragma unroll 1
        for (int i = 0; i < 64; i++) step(t0 + i, false);
        __syncthreads();                       // ring writes visible to chunk
        chunk(t0, 64);
        __syncthreads();                       // ring drained before overwrite
    }
    step(1024, true);
    __syncthreads();
    chunk(1024, 1);
    __syncthreads();

    // ---------------- epilogue: block reductions (7 warps) -----------------
    auto bred = [&](float v) -> float {
        #pragma unroll
        for (int o = 16; o > 0; o >>= 1) v += __shfl_down_sync(FULLM, v, o);
        if (lane == 0) red[w] = v;
        __syncthreads();
        float r = 0.0f;
        if (j == 0) {
            #pragma unroll
            for (int k = 0; k < 7; k++) r += red[k];
        }
        __syncthreads();
        return r;
    };

    float s;
    s = bred(acc0); if (j == 0) g_intA[b] = s;
    s = bred(acc1); if (j == 0) g_intB[b] = s;
    s = bred(am0);  if (j == 0) g_mskA[b] = s;
    s = bred(am1);  if (j == 0) g_mskB[b] = s;
    s = bred(accL); if (j == 0) g_loglam[b] = s;
    s = bred(accN); if (j == 0) g_nev[b] = s;
}

// ---------------- final: stitch integral groups + reduce scalars ----------
__global__ void __launch_bounds__(256)
k_final(const float* __restrict__ dur, float* __restrict__ out) {
    const int bb = threadIdx.x;     // one thread per group
    __shared__ float red[8];

    float lamsum = g_intA[bb] + (bb > 0 ? g_intB[bb - 1] : 0.0f);
    float msum   = g_mskA[bb] + (bb > 0 ? g_mskB[bb - 1] : 0.0f);
    float integ  = __fdividef(lamsum, msum) * dur[bb];
    float lp = g_loglam[bb] - integ;
    float nv = g_nev[bb];

    int wid = threadIdx.x >> 5, lid = threadIdx.x & 31;
    #pragma unroll
    for (int o = 16; o > 0; o >>= 1) lp += __shfl_down_sync(FULLM, lp, o);
    if (lid == 0) red[wid] = lp;
    __syncthreads();
    if (wid == 0) {
        float v = (lid < 8) ? red[lid] : 0.0f;
        #pragma unroll
        for (int o = 4; o > 0; o >>= 1) v += __shfl_down_sync(FULLM, v, o);
        if (lid == 0) out[0] = -v;
    }
    __syncthreads();
    #pragma unroll
    for (int o = 16; o > 0; o >>= 1) nv += __shfl_down_sync(FULLM, nv, o);
    if (lid == 0) red[wid] = nv;
    __syncthreads();
    if (wid == 0) {
        float v = (lid < 8) ? red[lid] : 0.0f;
        #pragma unroll
        for (int o = 4; o > 0; o >>= 1) v += __shfl_down_sync(FULLM, v, o);
        if (lid == 0) out[1] = v;
    }
}

// ---------------- launch ----------------
extern "C" void kernel_launch(void* const* d_in, const int* in_sizes, int n_in,
                              void* d_out, int out_size) {
    const int*   event = (const int*)  d_in[0];
    const float* dtime = (const float*)d_in[1];
    const float* dur   = (const float*)d_in[2];
    const float* dts   = (const float*)d_in[3];
    // d_in[4] = index_of_hidden_sampling (unused by the reference)
    const float* mask  = (const float*)d_in[5];
    const float* Emb   = (const float*)d_in[6];
    const float* W     = (const float*)d_in[7];
    const float* bias  = (const float*)d_in[8];
    const float* Wl    = (const float*)d_in[9];

    float* out = (float*)d_out;
    long long lam_elems = (long long)HN * 32;
    long long lamoff = (long long)out_size - lam_elems;
    if (lamoff < 0) lamoff = 0;
    float* lam_out = out + lamoff;

    static int attr_set = 0;
    if (!attr_set) {
        cudaFuncSetAttribute(k_scan, cudaFuncAttributeMaxDynamicSharedMemorySize,
                             SMEM_BYTES);
        attr_set = 1;
    }

    k_prex <<<NVOC, H7>>>(Emb, W, bias);
    k_scan <<<BB, NT, SMEM_BYTES>>>(event, dtime, W, Wl, dts, mask, lam_out);
    k_final<<<1, 256>>>(dur, out);
}